// round 6
// baseline (speedup 1.0000x reference)
#include <cuda_runtime.h>
#include <cstdint>
#include <math.h>

#define NNODES 87381
#define NLEAF  65536

// =================== scratch (device globals; no allocation) =================
// Tiled-interleaved layout for all GEMM A operands (128-row x 16-col chunks):
//   float index(row,k) = (rowblk*NCH + chunk)*2048 + ((s*128+m)*4 + c4)*2 + half
//   chunk=k>>4, kk=k&15, s=kk>>3, c4=kk&3, half=(kk&7)>>2, m=row&127.
__device__ float g_E2[688u * 19 * 2048];   // tf32-rounded embs, tiled (rows pad 88064)
__device__ float g_X [88064u * 640];       // x-projections [i|u|o|f], stride 640
__device__ float g_H2[683u * 10 * 2048];   // tf32-rounded h, tiled, 160-padded
__device__ float g_HS2[128u * 10 * 2048];  // tf32-rounded child-sum, tiled (16384 rows)
__device__ float g_C [NNODES * 150];       // cell states (exact fp32)
__device__ float g_P [16384u * 480];       // parent projections [i|u|o]
__device__ float g_F [65536u * 160];       // child f-projections
// B operands, fragment-row layout: [chunk][s][c4][col(640)][half] (rows of 1280 floats)
__device__ float g_Wxp[19 * 10240];        // Wx packed, tf32-rounded, K pad 304
__device__ float g_Whp[10 * 10240];        // Wh packed, tf32-rounded, K pad 160
__device__ float g_Wh2[160 * 640];         // Wh plain [k][i|u|o|f] for fused small levels
__device__ float g_bx[640];
__device__ float g_bh[640];

// =================== helpers ==================================================
__device__ __forceinline__ float to_tf32(float x) {
    unsigned u;
    asm("cvt.rna.tf32.f32 %0, %1;" : "=r"(u) : "f"(x));
    return __uint_as_float(u);
}
__device__ __forceinline__ float sigf(float x) {
    return __fdividef(1.0f, 1.0f + __expf(-x));
}
__device__ __forceinline__ float tanh_fast(float x) {
    return __fdividef(2.0f, 1.0f + __expf(-2.0f * x)) - 1.0f;
}
__device__ __forceinline__ size_t hpos(int row, int j) {
    int rb = row >> 7, m = row & 127;
    int chunk = j >> 4, kk = j & 15;
    int s = kk >> 3, r = kk & 7;
    return ((size_t)(rb * 10 + chunk) << 11) + (size_t)((((s << 7) + m) * 4 + (r & 3)) * 2 + (r >> 2));
}
__device__ __forceinline__ void mma8(float* d, const unsigned* a, const unsigned* b) {
    asm volatile(
        "mma.sync.aligned.m16n8k8.row.col.f32.tf32.tf32.f32 "
        "{%0,%1,%2,%3}, {%4,%5,%6,%7}, {%8,%9}, {%0,%1,%2,%3};\n"
        : "+f"(d[0]), "+f"(d[1]), "+f"(d[2]), "+f"(d[3])
        : "r"(a[0]), "r"(a[1]), "r"(a[2]), "r"(a[3]), "r"(b[0]), "r"(b[1]));
}
__device__ __forceinline__ void cp16(uint32_t dst, const void* src) {
    asm volatile("cp.async.ca.shared.global [%0], [%1], 16;" :: "r"(dst), "l"(src));
}
#define CP_COMMIT() asm volatile("cp.async.commit_group;" ::: "memory")
#define CP_WAIT2()  asm volatile("cp.async.wait_group 2;" ::: "memory")

// =================== embs -> tiled tf32 ======================================
__global__ void round_embs_kernel(const float* __restrict__ embs)
{
    int o2 = blockIdx.x * blockDim.x + threadIdx.x;     // float2 index
    const int TOT = 688 * 19 * 1024;
    if (o2 >= TOT) return;
    int w2 = o2 & 1023, t = o2 >> 10;
    int chunk = t % 19, rb = t / 19;
    int c4 = w2 & 3, m = (w2 >> 2) & 127, s = w2 >> 9;
    int row = (rb << 7) + m;
    int k = chunk * 16 + s * 8 + c4;                    // pair (k, k+4)
    float2 v = make_float2(0.f, 0.f);
    if (row < NNODES) {
        const float* er = embs + (size_t)row * 300;
        if (k < 300)     v.x = er[k];
        if (k + 4 < 300) v.y = er[k + 4];
    }
    v.x = to_tf32(v.x);
    v.y = to_tf32(v.y);
    ((float2*)g_E2)[o2] = v;
}

// =================== weight packing ==========================================
__global__ void pack_kernel(
    const float* Wix, const float* bix, const float* Wfx, const float* bfx,
    const float* Wux, const float* bux, const float* Wox, const float* box_,
    const float* Wih, const float* bih, const float* Wfh, const float* bfh,
    const float* Wuh, const float* buh, const float* Woh, const float* boh)
{
    const int T0 = 19 * 10240;          // Wxp
    const int T1 = T0 + 10 * 10240;     // Whp
    const int T2 = T1 + 160 * 640;      // Wh2
    const int T3 = T2 + 640;            // bx
    const int T4 = T3 + 640;            // bh
    for (int idx = blockIdx.x * blockDim.x + threadIdx.x; idx < T4;
         idx += gridDim.x * blockDim.x) {
        if (idx < T0) {
            int rowI = idx / 1280, w = idx % 1280;
            int col = w >> 1, half = w & 1;
            int chunk = rowI >> 3, rr = rowI & 7;
            int k = chunk * 16 + (rr >> 2) * 8 + half * 4 + (rr & 3);
            int m = col / 160, cc = col % 160;
            float v = 0.f;
            if (k < 300 && cc < 150) {
                const float* W = (m == 0) ? Wix : (m == 1) ? Wux : (m == 2) ? Wox : Wfx;
                v = W[k * 150 + cc];
            }
            g_Wxp[idx] = to_tf32(v);
        } else if (idx < T1) {
            int t = idx - T0;
            int rowI = t / 1280, w = t % 1280;
            int col = w >> 1, half = w & 1;
            int chunk = rowI >> 3, rr = rowI & 7;
            int k = chunk * 16 + (rr >> 2) * 8 + half * 4 + (rr & 3);
            int m = col / 160, cc = col % 160;
            float v = 0.f;
            if (k < 150 && cc < 150) {
                const float* W = (m == 0) ? Wih : (m == 1) ? Wuh : (m == 2) ? Woh : Wfh;
                v = W[k * 150 + cc];
            }
            g_Whp[t] = to_tf32(v);
        } else if (idx < T2) {
            int t = idx - T1;
            int k = t / 640, c = t % 640, m = c / 160, cc = c % 160;
            float v = 0.f;
            if (k < 150 && cc < 150) {
                const float* W = (m == 0) ? Wih : (m == 1) ? Wuh : (m == 2) ? Woh : Wfh;
                v = W[k * 150 + cc];
            }
            g_Wh2[t] = v;
        } else if (idx < T3) {
            int c = idx - T2, m = c / 160, cc = c % 160;
            float v = 0.f;
            if (cc < 150) {
                const float* b = (m == 0) ? bix : (m == 1) ? bux : (m == 2) ? box_ : bfx;
                v = b[cc];
            }
            g_bx[c] = v;
        } else {
            int c = idx - T3, m = c / 160, cc = c % 160;
            float v = 0.f;
            if (cc < 150) {
                const float* b = (m == 0) ? bih : (m == 1) ? buh : (m == 2) ? boh : bfh;
                v = b[cc];
            }
            g_bh[c] = v;
        }
    }
}

// =================== tf32 mma GEMM, BM=256 x BN=160, 3-stage cp.async =========
// 256 thr = 8 warps as 4m x 2n; warp tile 64x80 (4 m-frags x 10 n-frags).
// Stage = 6720 floats: A 2x2048 (two 128-row subtiles) + B 8 rows x 164 float2.
// skipM: blocks with colblk==480 and m0 < skipM exit (leaf f-gate skip).
template<bool BIAS>
__global__ __launch_bounds__(256, 1)
void gemm_tf32(const float* __restrict__ A2, int nch,
               const float* __restrict__ Bp, int col0,
               float* __restrict__ C, int ldc,
               const float* __restrict__ bias, int nchunk, int skipM)
{
    const int m0     = blockIdx.x * 256;
    const int colblk = blockIdx.y * 160;
    if (colblk == 480 && m0 < skipM) return;

    extern __shared__ __align__(16) float sm[];
    const uint32_t sbase = (uint32_t)__cvta_generic_to_shared(sm);

    const int tid    = threadIdx.x;
    const int lane   = tid & 31;
    const int wid    = tid >> 5;
    const int m_warp = (wid >> 1) * 64;
    const int n_warp = (wid & 1) * 80;
    const int bcol0  = col0 + colblk;
    const int c4     = lane & 3;
    const int q      = lane >> 2;

    float acc[4][10][4];
#pragma unroll
    for (int i = 0; i < 4; i++)
#pragma unroll
        for (int j = 0; j < 10; j++)
#pragma unroll
            for (int p = 0; p < 4; p++) acc[i][j][p] = 0.0f;

    auto issue = [&](int st, int ch) {
        if (ch < nchunk) {
            const uint32_t dbase = sbase + st * 26880;
#pragma unroll
            for (int e = 0; e < 4; e++) {
                int id = tid + e * 256;
                int t = id >> 9, off = id & 511;
                cp16(dbase + id * 16,
                     A2 + ((size_t)(2 * blockIdx.x + t) * nch + ch) * 2048 + off * 4);
            }
            const float* Bt = Bp + (size_t)ch * 10240 + (size_t)bcol0 * 2;
#pragma unroll
            for (int e = 0; e < 3; e++) {
                int id = tid + e * 256;
                if (id < 640) {
                    int r = id / 80, o = id - r * 80;
                    cp16(dbase + 16384 + r * 1312 + o * 16, Bt + r * 1280 + o * 4);
                }
            }
        }
        CP_COMMIT();
    };

    issue(0, 0);
    issue(1, 1);
    issue(2, 2);

    const int sub = m_warp >> 7;           // 0 or 1 (128-row subtile)
    const int ml  = (m_warp & 127) + q;    // row within subtile

    int st = 0;
    for (int ch = 0; ch < nchunk; ch++) {
        CP_WAIT2();
        __syncthreads();
        const float* stf = sm + st * 6720;
        const float2* Af = (const float2*)stf + sub * 1024;
        const float2* Bf = (const float2*)(stf + 4096);

#pragma unroll
        for (int s = 0; s < 2; s++) {
            unsigned b[10][2];
#pragma unroll
            for (int j = 0; j < 10; j++) {
                float2 bv = Bf[(s * 4 + c4) * 164 + n_warp + q + 8 * j];
                b[j][0] = __float_as_uint(bv.x);
                b[j][1] = __float_as_uint(bv.y);
            }
#pragma unroll
            for (int i = 0; i < 4; i++) {
                int m1 = ml + 16 * i;
                float2 lo = Af[(s * 128 + m1) * 4 + c4];
                float2 hi = Af[(s * 128 + m1 + 8) * 4 + c4];
                unsigned a[4];
                a[0] = __float_as_uint(lo.x);
                a[1] = __float_as_uint(hi.x);
                a[2] = __float_as_uint(lo.y);
                a[3] = __float_as_uint(hi.y);
#pragma unroll
                for (int j = 0; j < 10; j++) mma8(acc[i][j], a, b[j]);
            }
        }
        __syncthreads();
        issue(st, ch + 3);
        st = (st == 2) ? 0 : st + 1;
    }

    // epilogue (all M padded to 256-row multiples: unguarded)
    const int r0 = m0 + m_warp + q;
    const int cl = n_warp + c4 * 2;
#pragma unroll
    for (int i = 0; i < 4; i++) {
#pragma unroll
        for (int h = 0; h < 2; h++) {
            int r = r0 + 16 * i + 8 * h;
            float* crow = C + (size_t)r * ldc + colblk;
#pragma unroll
            for (int j = 0; j < 10; j++) {
                int c = cl + 8 * j;
                float2 v = make_float2(acc[i][j][2 * h], acc[i][j][2 * h + 1]);
                if (BIAS) {
                    v.x += bias[bcol0 + c];
                    v.y += bias[bcol0 + c + 1];
                }
                *(float2*)(crow + c) = v;
            }
        }
    }
}

// =================== child-sum of h (tiled -> tiled, tf32) ====================
__global__ void hsum_kernel(int off_c, int n)
{
    int o2 = blockIdx.x * blockDim.x + threadIdx.x;     // float2 index into HS2
    const int TOT = (n >> 7) * 10 * 1024;
    if (o2 >= TOT) return;
    int w2 = o2 & 1023, t = o2 >> 10;
    int chunk = t % 10, rb = t / 10;
    int c4 = w2 & 3, m = (w2 >> 2) & 127, s = w2 >> 9;
    int p = (rb << 7) + m;
    const float2* H2 = (const float2*)g_H2;
    float2 a = make_float2(0.f, 0.f);
#pragma unroll
    for (int k = 0; k < 4; k++) {
        int crow = off_c + 4 * p + k;
        float2 hv = H2[((size_t)((crow >> 7) * 10 + chunk) << 10) +
                       (size_t)(((s << 7) + (crow & 127)) * 4 + c4)];
        a.x += hv.x;
        a.y += hv.y;
    }
    a.x = to_tf32(a.x);
    a.y = to_tf32(a.y);
    ((float2*)g_HS2)[o2] = a;
}

// =================== leaves ====================================================
__global__ void leaf_kernel(float* __restrict__ out)
{
    int idx = blockIdx.x * blockDim.x + threadIdx.x;
    if (idx >= NLEAF * 160) return;
    int p = idx / 160, j = idx - p * 160;
    if (j >= 150) { g_H2[hpos(p, j)] = 0.0f; return; }
    const float* Xr = g_X + (size_t)p * 640;
    float ig = sigf(Xr[j] + g_bh[j]);
    float ug = tanh_fast(Xr[160 + j] + g_bh[160 + j]);
    float og = sigf(Xr[320 + j] + g_bh[320 + j]);
    float c = ig * ug;
    g_C[(size_t)p * 150 + j] = c;
    float h = og * tanh_fast(c);
    out[(size_t)p * 150 + j] = h;
    g_H2[hpos(p, j)] = to_tf32(h);
}

// =================== internal level (GEMM path, d=1..3) ========================
__global__ void level_kernel(float* __restrict__ out, int off_p, int off_c, int n)
{
    int idx = blockIdx.x * blockDim.x + threadIdx.x;
    if (idx >= n * 160) return;
    int p = idx / 160, j = idx - p * 160;
    int g = off_p + p;
    if (j >= 150) { g_H2[hpos(g, j)] = 0.0f; return; }
    const float* Xr = g_X + (size_t)g * 640;
    const float* Pr = g_P + (size_t)p * 480;

    float ig = sigf(Xr[j]        + Pr[j]       + g_bh[j]);
    float ug = tanh_fast(Xr[160 + j] + Pr[160 + j] + g_bh[160 + j]);
    float og = sigf(Xr[320 + j]  + Pr[320 + j] + g_bh[320 + j]);
    float xf = Xr[480 + j] + g_bh[480 + j];

    float fc = 0.0f;
#pragma unroll
    for (int k = 0; k < 4; k++) {
        int cl = 4 * p + k;
        float f = sigf(xf + g_F[(size_t)cl * 160 + j]);
        fc = fmaf(f, g_C[(size_t)(off_c + cl) * 150 + j], fc);
    }
    float c = fmaf(ig, ug, fc);
    g_C[(size_t)g * 150 + j] = c;
    float h = og * tanh_fast(c);
    out[(size_t)g * 150 + j] = h;
    g_H2[hpos(g, j)] = to_tf32(h);
}

// =================== fused small level (d=4..8, n<=256) ========================
__global__ __launch_bounds__(160)
void small_level_kernel(float* __restrict__ out, int off_p, int off_c)
{
    int p = blockIdx.x, j = threadIdx.x;
    __shared__ float hs[160];
    __shared__ float hch[4][160];
    int g = off_p + p;
    float h0 = g_H2[hpos(off_c + 4 * p + 0, j)];
    float h1 = g_H2[hpos(off_c + 4 * p + 1, j)];
    float h2 = g_H2[hpos(off_c + 4 * p + 2, j)];
    float h3 = g_H2[hpos(off_c + 4 * p + 3, j)];
    hch[0][j] = h0; hch[1][j] = h1; hch[2][j] = h2; hch[3][j] = h3;
    hs[j] = h0 + h1 + h2 + h3;
    __syncthreads();

    float di = 0.f, du = 0.f, dog = 0.f;
    float df0 = 0.f, df1 = 0.f, df2 = 0.f, df3 = 0.f;
#pragma unroll 4
    for (int m = 0; m < 160; m++) {
        float hm = hs[m];
        const float* wrow = g_Wh2 + m * 640;
        di  = fmaf(hm, wrow[j], di);
        du  = fmaf(hm, wrow[160 + j], du);
        dog = fmaf(hm, wrow[320 + j], dog);
        float wf = wrow[480 + j];
        df0 = fmaf(hch[0][m], wf, df0);
        df1 = fmaf(hch[1][m], wf, df1);
        df2 = fmaf(hch[2][m], wf, df2);
        df3 = fmaf(hch[3][m], wf, df3);
    }
    if (j < 150) {
        const float* Xr = g_X + (size_t)g * 640;
        float ig = sigf(Xr[j] + di + g_bh[j]);
        float ug = tanh_fast(Xr[160 + j] + du + g_bh[160 + j]);
        float og = sigf(Xr[320 + j] + dog + g_bh[320 + j]);
        float xf = Xr[480 + j] + g_bh[480 + j];
        float fc = sigf(xf + df0) * g_C[(size_t)(off_c + 4 * p + 0) * 150 + j]
                 + sigf(xf + df1) * g_C[(size_t)(off_c + 4 * p + 1) * 150 + j]
                 + sigf(xf + df2) * g_C[(size_t)(off_c + 4 * p + 2) * 150 + j]
                 + sigf(xf + df3) * g_C[(size_t)(off_c + 4 * p + 3) * 150 + j];
        float c = fmaf(ig, ug, fc);
        g_C[(size_t)g * 150 + j] = c;
        float h = og * tanh_fast(c);
        out[(size_t)g * 150 + j] = h;
        g_H2[hpos(g, j)] = to_tf32(h);
    } else {
        g_H2[hpos(g, j)] = 0.0f;
    }
}

// =================== host orchestration ========================================
extern "C" void kernel_launch(void* const* d_in, const int* in_sizes, int n_in,
                              void* d_out, int out_size)
{
    const float* embs = (const float*)d_in[0];
    const float* Wix = (const float*)d_in[1];  const float* bix = (const float*)d_in[2];
    const float* Wfx = (const float*)d_in[3];  const float* bfx = (const float*)d_in[4];
    const float* Wux = (const float*)d_in[5];  const float* bux = (const float*)d_in[6];
    const float* Wox = (const float*)d_in[7];  const float* box_ = (const float*)d_in[8];
    const float* Wih = (const float*)d_in[9];  const float* bih = (const float*)d_in[10];
    const float* Wfh = (const float*)d_in[11]; const float* bfh = (const float*)d_in[12];
    const float* Wuh = (const float*)d_in[13]; const float* buh = (const float*)d_in[14];
    const float* Woh = (const float*)d_in[15]; const float* boh = (const float*)d_in[16];
    float* out = (float*)d_out;

    float *pE2, *pX, *pH2, *pHS2, *pWxp, *pWhp, *pbx, *pP, *pF;
    cudaGetSymbolAddress((void**)&pE2,  g_E2);
    cudaGetSymbolAddress((void**)&pX,   g_X);
    cudaGetSymbolAddress((void**)&pH2,  g_H2);
    cudaGetSymbolAddress((void**)&pHS2, g_HS2);
    cudaGetSymbolAddress((void**)&pWxp, g_Wxp);
    cudaGetSymbolAddress((void**)&pWhp, g_Whp);
    cudaGetSymbolAddress((void**)&pbx,  g_bx);
    cudaGetSymbolAddress((void**)&pP,   g_P);
    cudaGetSymbolAddress((void**)&pF,   g_F);

    static const int SIZES[9] = {65536, 16384, 4096, 1024, 256, 64, 16, 4, 1};
    static const int OFF[9]   = {0, 65536, 81920, 86016, 87040, 87296, 87360, 87376, 87380};
    const int SMEM = 3 * 6720 * 4;  // 80640 B

    cudaFuncSetAttribute(gemm_tf32<true>,
                         cudaFuncAttributeMaxDynamicSharedMemorySize, SMEM);
    cudaFuncSetAttribute(gemm_tf32<false>,
                         cudaFuncAttributeMaxDynamicSharedMemorySize, SMEM);

    // 1. pre-round + tile embs; pack weights
    round_embs_kernel<<<(688 * 19 * 1024 + 255) / 256, 256>>>(embs);
    pack_kernel<<<512, 256>>>(Wix, bix, Wfx, bfx, Wux, bux, Wox, box_,
                              Wih, bih, Wfh, bfh, Wuh, buh, Woh, boh);

    // 2. X projections, single launch: blocks x<256 (leaf rows) skip f-gate col
    {
        dim3 grid(344, 4);
        gemm_tf32<true><<<grid, 256, SMEM>>>(pE2, 19, pWxp, 0, pX, 640, pbx, 19, NLEAF);
    }

    // 3. leaves
    leaf_kernel<<<(NLEAF * 160 + 255) / 256, 256>>>(out);

    // 4. levels 1..3: GEMM path
    for (int d = 1; d <= 3; d++) {
        int n  = SIZES[d];
        int np = SIZES[d - 1];
        hsum_kernel<<<((n >> 7) * 10 * 1024 + 255) / 256, 256>>>(OFF[d - 1], n);
        {   // P = h_sum @ [W_ih|W_uh|W_oh]
            dim3 grid(n / 256, 3);
            gemm_tf32<false><<<grid, 256, SMEM>>>(pHS2, 10, pWhp, 0, pP, 480,
                                                  nullptr, 10, 0);
        }
        {   // F = h_children @ W_fh  (B cols 480..639)
            dim3 grid(np / 256, 1);
            gemm_tf32<false><<<grid, 256, SMEM>>>(pH2 + (size_t)OFF[d - 1] * 160, 10,
                                                  pWhp, 480, pF, 160, nullptr, 10, 0);
        }
        level_kernel<<<(n * 160 + 255) / 256, 256>>>(out, OFF[d], OFF[d - 1], n);
    }

    // 5. levels 4..8: fused fp32 kernels (n = 256, 64, 16, 4, 1)
    for (int d = 4; d <= 8; d++)
        small_level_kernel<<<SIZES[d], 160>>>(out, OFF[d], OFF[d - 1]);
}

// round 7
// speedup vs baseline: 1.0628x; 1.0628x over previous
#include <cuda_runtime.h>
#include <cstdint>
#include <math.h>

#define NNODES 87381
#define NLEAF  65536

// =================== scratch (device globals; no allocation) =================
// Tiled-interleaved layout for all GEMM A operands (128-row x 16-col chunks):
//   float index(row,k) = (rowblk*NCH + chunk)*2048 + ((s*128+m)*4 + c4)*2 + half
//   chunk=k>>4, kk=k&15, s=kk>>3, c4=kk&3, half=(kk&7)>>2, m=row&127.
__device__ float g_E2[688u * 19 * 2048];   // tf32-rounded embs, tiled (rows pad 88064)
__device__ float g_X [88064u * 640];       // x-projections [i|u|o|f] (internal rows only)
__device__ float g_H2[683u * 10 * 2048];   // tf32-rounded h, tiled, 160-padded (pads stay 0)
__device__ float g_HS2[128u * 10 * 2048];  // tf32-rounded child-sum, tiled
__device__ float g_C [NNODES * 150];       // cell states (exact fp32)
__device__ float g_P [16384u * 480];       // parent projections [i|u|o]
__device__ float g_F [65536u * 160];       // child f-projections
// B operands, fragment-row layout: [chunk][s][c4][col(640)][half] (rows of 1280 floats)
__device__ float g_Wxp[19 * 10240];        // Wx packed, tf32-rounded, K pad 304
__device__ float g_Whp[10 * 10240];        // Wh packed, tf32-rounded, K pad 160
__device__ float g_Wh2[160 * 640];         // Wh plain [k][i|u|o|f] for fused small levels
__device__ float g_bx[640];
__device__ float g_bh[640];

// =================== helpers ==================================================
__device__ __forceinline__ float to_tf32(float x) {
    unsigned u;
    asm("cvt.rna.tf32.f32 %0, %1;" : "=r"(u) : "f"(x));
    return __uint_as_float(u);
}
__device__ __forceinline__ float sigf(float x) {
    return __fdividef(1.0f, 1.0f + __expf(-x));
}
__device__ __forceinline__ float tanh_fast(float x) {
    return __fdividef(2.0f, 1.0f + __expf(-2.0f * x)) - 1.0f;
}
__device__ __forceinline__ size_t hpos(int row, int j) {
    int rb = row >> 7, m = row & 127;
    int chunk = j >> 4, kk = j & 15;
    int s = kk >> 3, r = kk & 7;
    return ((size_t)(rb * 10 + chunk) << 11) + (size_t)((((s << 7) + m) * 4 + (r & 3)) * 2 + (r >> 2));
}
__device__ __forceinline__ void mma8(float* d, const unsigned* a, const unsigned* b) {
    asm volatile(
        "mma.sync.aligned.m16n8k8.row.col.f32.tf32.tf32.f32 "
        "{%0,%1,%2,%3}, {%4,%5,%6,%7}, {%8,%9}, {%0,%1,%2,%3};\n"
        : "+f"(d[0]), "+f"(d[1]), "+f"(d[2]), "+f"(d[3])
        : "r"(a[0]), "r"(a[1]), "r"(a[2]), "r"(a[3]), "r"(b[0]), "r"(b[1]));
}
__device__ __forceinline__ void cp16(uint32_t dst, const void* src) {
    asm volatile("cp.async.ca.shared.global [%0], [%1], 16;" :: "r"(dst), "l"(src));
}
#define CP_COMMIT() asm volatile("cp.async.commit_group;" ::: "memory")
#define CP_WAIT2()  asm volatile("cp.async.wait_group 2;" ::: "memory")

// =================== embs -> tiled tf32 ======================================
__global__ void round_embs_kernel(const float* __restrict__ embs)
{
    int o2 = blockIdx.x * blockDim.x + threadIdx.x;     // float2 index
    const int TOT = 688 * 19 * 1024;
    if (o2 >= TOT) return;
    int w2 = o2 & 1023, t = o2 >> 10;
    int chunk = t % 19, rb = t / 19;
    int c4 = w2 & 3, m = (w2 >> 2) & 127, s = w2 >> 9;
    int row = (rb << 7) + m;
    int k = chunk * 16 + s * 8 + c4;                    // pair (k, k+4)
    float2 v = make_float2(0.f, 0.f);
    if (row < NNODES) {
        const float* er = embs + (size_t)row * 300;
        if (k < 300)     v.x = er[k];
        if (k + 4 < 300) v.y = er[k + 4];
    }
    v.x = to_tf32(v.x);
    v.y = to_tf32(v.y);
    ((float2*)g_E2)[o2] = v;
}

// =================== weight packing ==========================================
__global__ void pack_kernel(
    const float* Wix, const float* bix, const float* Wfx, const float* bfx,
    const float* Wux, const float* bux, const float* Wox, const float* box_,
    const float* Wih, const float* bih, const float* Wfh, const float* bfh,
    const float* Wuh, const float* buh, const float* Woh, const float* boh)
{
    const int T0 = 19 * 10240;          // Wxp
    const int T1 = T0 + 10 * 10240;     // Whp
    const int T2 = T1 + 160 * 640;      // Wh2
    const int T3 = T2 + 640;            // bx
    const int T4 = T3 + 640;            // bh
    for (int idx = blockIdx.x * blockDim.x + threadIdx.x; idx < T4;
         idx += gridDim.x * blockDim.x) {
        if (idx < T0) {
            int rowI = idx / 1280, w = idx % 1280;
            int col = w >> 1, half = w & 1;
            int chunk = rowI >> 3, rr = rowI & 7;
            int k = chunk * 16 + (rr >> 2) * 8 + half * 4 + (rr & 3);
            int m = col / 160, cc = col % 160;
            float v = 0.f;
            if (k < 300 && cc < 150) {
                const float* W = (m == 0) ? Wix : (m == 1) ? Wux : (m == 2) ? Wox : Wfx;
                v = W[k * 150 + cc];
            }
            g_Wxp[idx] = to_tf32(v);
        } else if (idx < T1) {
            int t = idx - T0;
            int rowI = t / 1280, w = t % 1280;
            int col = w >> 1, half = w & 1;
            int chunk = rowI >> 3, rr = rowI & 7;
            int k = chunk * 16 + (rr >> 2) * 8 + half * 4 + (rr & 3);
            int m = col / 160, cc = col % 160;
            float v = 0.f;
            if (k < 150 && cc < 150) {
                const float* W = (m == 0) ? Wih : (m == 1) ? Wuh : (m == 2) ? Woh : Wfh;
                v = W[k * 150 + cc];
            }
            g_Whp[t] = to_tf32(v);
        } else if (idx < T2) {
            int t = idx - T1;
            int k = t / 640, c = t % 640, m = c / 160, cc = c % 160;
            float v = 0.f;
            if (k < 150 && cc < 150) {
                const float* W = (m == 0) ? Wih : (m == 1) ? Wuh : (m == 2) ? Woh : Wfh;
                v = W[k * 150 + cc];
            }
            g_Wh2[t] = v;
        } else if (idx < T3) {
            int c = idx - T2, m = c / 160, cc = c % 160;
            float v = 0.f;
            if (cc < 150) {
                const float* b = (m == 0) ? bix : (m == 1) ? bux : (m == 2) ? box_ : bfx;
                v = b[cc];
            }
            g_bx[c] = v;
        } else {
            int c = idx - T3, m = c / 160, cc = c % 160;
            float v = 0.f;
            if (cc < 150) {
                const float* b = (m == 0) ? bih : (m == 1) ? buh : (m == 2) ? boh : bfh;
                v = b[cc];
            }
            g_bh[c] = v;
        }
    }
}

// =================== generic tf32 mma GEMM (R5 config) ========================
// BM=128, BN=160, 3-stage cp.async, 256 thr = 8 warps (2m x 4n), warp 64x40.
template<bool BIAS>
__global__ __launch_bounds__(256, 2)
void gemm_tf32(const float* __restrict__ A2, int nch,
               const float* __restrict__ Bp, int col0,
               float* __restrict__ C, int ldc,
               const float* __restrict__ bias, int nchunk)
{
    extern __shared__ __align__(16) float sm[];
    const uint32_t sbase = (uint32_t)__cvta_generic_to_shared(sm);

    const int tid    = threadIdx.x;
    const int lane   = tid & 31;
    const int wid    = tid >> 5;
    const int m_warp = (wid >> 2) * 64;
    const int n_warp = (wid & 3) * 40;
    const int m0     = blockIdx.x * 128;
    const int colblk = blockIdx.y * 160;
    const int bcol0  = col0 + colblk;
    const int c4     = lane & 3;
    const int q      = lane >> 2;

    float acc[4][5][4];
#pragma unroll
    for (int i = 0; i < 4; i++)
#pragma unroll
        for (int j = 0; j < 5; j++)
#pragma unroll
            for (int p = 0; p < 4; p++) acc[i][j][p] = 0.0f;

    auto issue = [&](int st, int ch) {
        if (ch < nchunk) {
            const float* At = A2 + ((size_t)blockIdx.x * nch + ch) * 2048;
            uint32_t da = sbase + st * 18688 + tid * 16;
            cp16(da, At + tid * 4);
            cp16(da + 4096, At + tid * 4 + 1024);
            const float* Bt = Bp + (size_t)ch * 10240 + (size_t)bcol0 * 2;
#pragma unroll
            for (int e = 0; e < 3; e++) {
                int id = tid + e * 256;
                if (id < 640) {
                    int r = id / 80, o = id - r * 80;
                    cp16(sbase + st * 18688 + 8192 + r * 1312 + o * 16,
                         Bt + r * 1280 + o * 4);
                }
            }
        }
        CP_COMMIT();
    };

    issue(0, 0);
    issue(1, 1);
    issue(2, 2);

    int st = 0;
    for (int ch = 0; ch < nchunk; ch++) {
        CP_WAIT2();
        __syncthreads();
        const float* stf = sm + st * 4672;
        const float2* Af = (const float2*)stf;
        const float2* Bf = (const float2*)(stf + 2048);

#pragma unroll
        for (int s = 0; s < 2; s++) {
            unsigned a[4][4];
#pragma unroll
            for (int i = 0; i < 4; i++) {
                int m1 = m_warp + 16 * i + q;
                float2 lo = Af[(s * 128 + m1) * 4 + c4];
                float2 hi = Af[(s * 128 + m1 + 8) * 4 + c4];
                a[i][0] = __float_as_uint(lo.x);
                a[i][1] = __float_as_uint(hi.x);
                a[i][2] = __float_as_uint(lo.y);
                a[i][3] = __float_as_uint(hi.y);
            }
            unsigned b[5][2];
#pragma unroll
            for (int j = 0; j < 5; j++) {
                float2 bv = Bf[(s * 4 + c4) * 164 + n_warp + q + 8 * j];
                b[j][0] = __float_as_uint(bv.x);
                b[j][1] = __float_as_uint(bv.y);
            }
#pragma unroll
            for (int i = 0; i < 4; i++)
#pragma unroll
                for (int j = 0; j < 5; j++) mma8(acc[i][j], a[i], b[j]);
        }
        __syncthreads();
        issue(st, ch + 3);
        st = (st == 2) ? 0 : st + 1;
    }

    const int r0 = m0 + m_warp + q;
    const int cl = n_warp + c4 * 2;
#pragma unroll
    for (int i = 0; i < 4; i++) {
#pragma unroll
        for (int h = 0; h < 2; h++) {
            int r = r0 + 16 * i + 8 * h;
            float* crow = C + (size_t)r * ldc + colblk;
#pragma unroll
            for (int j = 0; j < 5; j++) {
                int c = cl + 8 * j;
                float2 v = make_float2(acc[i][j][2 * h], acc[i][j][2 * h + 1]);
                if (BIAS) {
                    v.x += bias[bcol0 + c];
                    v.y += bias[bcol0 + c + 1];
                }
                *(float2*)(crow + c) = v;
            }
        }
    }
}

// =================== leaf-fused GEMM: X-proj + gates in one kernel ============
// BM=64, all 3 gate blocks (i,u,o) per CTA. 256 thr = 8 warps (2m x 4n),
// warp tile 32 x (40 per gate). Epilogue computes c,h and writes C/out/H2
// directly — no X round-trip for the 65536 leaves.
// Stage = 8896 floats: A 1024 + 3 gates x (8 rows x 164 float2).
__global__ __launch_bounds__(256, 1)
void gemm_leaf(const float* __restrict__ A2, const float* __restrict__ Bp,
               float* __restrict__ out)
{
    extern __shared__ __align__(16) float sm[];
    const uint32_t sbase = (uint32_t)__cvta_generic_to_shared(sm);
    const int STG = 8896;                 // floats per stage
    const int tid  = threadIdx.x;
    const int lane = tid & 31;
    const int wid  = tid >> 5;
    const int m_warp = (wid >> 2) * 32;
    const int n_warp = (wid & 3) * 40;
    const int rb   = blockIdx.x >> 1;     // 128-row block in E2
    const int half = blockIdx.x & 1;      // which 64-row half
    const int c4   = lane & 3;
    const int q    = lane >> 2;

    float acc[2][3][5][4];
#pragma unroll
    for (int i = 0; i < 2; i++)
#pragma unroll
        for (int g = 0; g < 3; g++)
#pragma unroll
            for (int j = 0; j < 5; j++)
#pragma unroll
                for (int p = 0; p < 4; p++) acc[i][g][j][p] = 0.0f;

    auto issue = [&](int st, int ch) {
        if (ch < 19) {
            const uint32_t dbase = sbase + st * (STG * 4);
            {   // A half-tile: 1024 floats (s-region 512 each)
                int s = tid >> 7, o = tid & 127;
                cp16(dbase + tid * 16,
                     A2 + ((size_t)(rb * 19 + ch) << 11) + s * 1024 + half * 512 + o * 4);
            }
            const float* Bt = Bp + (size_t)ch * 10240;
#pragma unroll
            for (int e = 0; e < 8; e++) {
                int id = tid + e * 256;
                if (id < 1920) {
                    int g = id / 640, w = id - g * 640;
                    int r = w / 80, o = w - r * 80;
                    cp16(dbase + 4096 + g * 10496 + r * 1312 + o * 16,
                         Bt + g * 320 + r * 1280 + o * 4);
                }
            }
        }
        CP_COMMIT();
    };

    issue(0, 0);
    issue(1, 1);
    issue(2, 2);

    int st = 0;
    for (int ch = 0; ch < 19; ch++) {
        CP_WAIT2();
        __syncthreads();
        const float* stf = sm + st * STG;
        const float2* Af = (const float2*)stf;
        const float2* Bf = (const float2*)(stf + 1024);

#pragma unroll
        for (int s = 0; s < 2; s++) {
            unsigned b[3][5][2];
#pragma unroll
            for (int g = 0; g < 3; g++)
#pragma unroll
                for (int j = 0; j < 5; j++) {
                    float2 bv = Bf[g * 1312 + (s * 4 + c4) * 164 + n_warp + q + 8 * j];
                    b[g][j][0] = __float_as_uint(bv.x);
                    b[g][j][1] = __float_as_uint(bv.y);
                }
#pragma unroll
            for (int i = 0; i < 2; i++) {
                int m1 = m_warp + 16 * i + q;
                float2 lo = Af[(s * 64 + m1) * 4 + c4];
                float2 hi = Af[(s * 64 + m1 + 8) * 4 + c4];
                unsigned a[4];
                a[0] = __float_as_uint(lo.x);
                a[1] = __float_as_uint(hi.x);
                a[2] = __float_as_uint(lo.y);
                a[3] = __float_as_uint(hi.y);
#pragma unroll
                for (int g = 0; g < 3; g++)
#pragma unroll
                    for (int j = 0; j < 5; j++) mma8(acc[i][g][j], a, b[g][j]);
            }
        }
        __syncthreads();
        issue(st, ch + 3);
        st = (st == 2) ? 0 : st + 1;
    }

    // ---- fused leaf epilogue: c = sig(i)*tanh(u); h = sig(o)*tanh(c) ----
    float bi[10], bu[10], bo[10];
#pragma unroll
    for (int j = 0; j < 5; j++)
#pragma unroll
        for (int e = 0; e < 2; e++) {
            int col = n_warp + c4 * 2 + 8 * j + e;
            bi[2 * j + e] = g_bx[col]       + g_bh[col];
            bu[2 * j + e] = g_bx[160 + col] + g_bh[160 + col];
            bo[2 * j + e] = g_bx[320 + col] + g_bh[320 + col];
        }

    const int r0 = blockIdx.x * 64 + m_warp + q;
#pragma unroll
    for (int i = 0; i < 2; i++) {
#pragma unroll
        for (int h = 0; h < 2; h++) {
            int r = r0 + 16 * i + 8 * h;
#pragma unroll
            for (int j = 0; j < 5; j++) {
#pragma unroll
                for (int e = 0; e < 2; e++) {
                    int col = n_warp + c4 * 2 + 8 * j + e;
                    if (col < 150) {
                        float vi = acc[i][0][j][2 * h + e] + bi[2 * j + e];
                        float vu = acc[i][1][j][2 * h + e] + bu[2 * j + e];
                        float vo = acc[i][2][j][2 * h + e] + bo[2 * j + e];
                        float ig = sigf(vi);
                        float ug = tanh_fast(vu);
                        float og = sigf(vo);
                        float cv = ig * ug;
                        float hv = og * tanh_fast(cv);
                        g_C[(size_t)r * 150 + col] = cv;
                        out[(size_t)r * 150 + col] = hv;
                        g_H2[hpos(r, col)] = to_tf32(hv);
                    }
                }
            }
        }
    }
}

// =================== child-sum of h (tiled -> tiled, tf32) ====================
__global__ void hsum_kernel(int off_c, int n)
{
    int o2 = blockIdx.x * blockDim.x + threadIdx.x;     // float2 index into HS2
    const int TOT = (n >> 7) * 10 * 1024;
    if (o2 >= TOT) return;
    int w2 = o2 & 1023, t = o2 >> 10;
    int chunk = t % 10, rb = t / 10;
    int c4 = w2 & 3, m = (w2 >> 2) & 127, s = w2 >> 9;
    int p = (rb << 7) + m;
    const float2* H2 = (const float2*)g_H2;
    float2 a = make_float2(0.f, 0.f);
#pragma unroll
    for (int k = 0; k < 4; k++) {
        int crow = off_c + 4 * p + k;
        float2 hv = H2[((size_t)((crow >> 7) * 10 + chunk) << 10) +
                       (size_t)(((s << 7) + (crow & 127)) * 4 + c4)];
        a.x += hv.x;
        a.y += hv.y;
    }
    a.x = to_tf32(a.x);
    a.y = to_tf32(a.y);
    ((float2*)g_HS2)[o2] = a;
}

// =================== internal level (GEMM path, d=1..3) ========================
__global__ void level_kernel(float* __restrict__ out, int off_p, int off_c, int n)
{
    int idx = blockIdx.x * blockDim.x + threadIdx.x;
    if (idx >= n * 160) return;
    int p = idx / 160, j = idx - p * 160;
    int g = off_p + p;
    if (j >= 150) { g_H2[hpos(g, j)] = 0.0f; return; }
    const float* Xr = g_X + (size_t)g * 640;
    const float* Pr = g_P + (size_t)p * 480;

    float ig = sigf(Xr[j]        + Pr[j]       + g_bh[j]);
    float ug = tanh_fast(Xr[160 + j] + Pr[160 + j] + g_bh[160 + j]);
    float og = sigf(Xr[320 + j]  + Pr[320 + j] + g_bh[320 + j]);
    float xf = Xr[480 + j] + g_bh[480 + j];

    float fc = 0.0f;
#pragma unroll
    for (int k = 0; k < 4; k++) {
        int cl = 4 * p + k;
        float f = sigf(xf + g_F[(size_t)cl * 160 + j]);
        fc = fmaf(f, g_C[(size_t)(off_c + cl) * 150 + j], fc);
    }
    float c = fmaf(ig, ug, fc);
    g_C[(size_t)g * 150 + j] = c;
    float h = og * tanh_fast(c);
    out[(size_t)g * 150 + j] = h;
    g_H2[hpos(g, j)] = to_tf32(h);
}

// =================== fused small level (d=4..8, n<=256) ========================
__global__ __launch_bounds__(160)
void small_level_kernel(float* __restrict__ out, int off_p, int off_c)
{
    int p = blockIdx.x, j = threadIdx.x;
    __shared__ float hs[160];
    __shared__ float hch[4][160];
    int g = off_p + p;
    float h0 = g_H2[hpos(off_c + 4 * p + 0, j)];
    float h1 = g_H2[hpos(off_c + 4 * p + 1, j)];
    float h2 = g_H2[hpos(off_c + 4 * p + 2, j)];
    float h3 = g_H2[hpos(off_c + 4 * p + 3, j)];
    hch[0][j] = h0; hch[1][j] = h1; hch[2][j] = h2; hch[3][j] = h3;
    hs[j] = h0 + h1 + h2 + h3;
    __syncthreads();

    float di = 0.f, du = 0.f, dog = 0.f;
    float df0 = 0.f, df1 = 0.f, df2 = 0.f, df3 = 0.f;
#pragma unroll 4
    for (int m = 0; m < 160; m++) {
        float hm = hs[m];
        const float* wrow = g_Wh2 + m * 640;
        di  = fmaf(hm, wrow[j], di);
        du  = fmaf(hm, wrow[160 + j], du);
        dog = fmaf(hm, wrow[320 + j], dog);
        float wf = wrow[480 + j];
        df0 = fmaf(hch[0][m], wf, df0);
        df1 = fmaf(hch[1][m], wf, df1);
        df2 = fmaf(hch[2][m], wf, df2);
        df3 = fmaf(hch[3][m], wf, df3);
    }
    if (j < 150) {
        const float* Xr = g_X + (size_t)g * 640;
        float ig = sigf(Xr[j] + di + g_bh[j]);
        float ug = tanh_fast(Xr[160 + j] + du + g_bh[160 + j]);
        float og = sigf(Xr[320 + j] + dog + g_bh[320 + j]);
        float xf = Xr[480 + j] + g_bh[480 + j];
        float fc = sigf(xf + df0) * g_C[(size_t)(off_c + 4 * p + 0) * 150 + j]
                 + sigf(xf + df1) * g_C[(size_t)(off_c + 4 * p + 1) * 150 + j]
                 + sigf(xf + df2) * g_C[(size_t)(off_c + 4 * p + 2) * 150 + j]
                 + sigf(xf + df3) * g_C[(size_t)(off_c + 4 * p + 3) * 150 + j];
        float c = fmaf(ig, ug, fc);
        g_C[(size_t)g * 150 + j] = c;
        float h = og * tanh_fast(c);
        out[(size_t)g * 150 + j] = h;
        g_H2[hpos(g, j)] = to_tf32(h);
    } else {
        g_H2[hpos(g, j)] = 0.0f;
    }
}

// =================== host orchestration ========================================
extern "C" void kernel_launch(void* const* d_in, const int* in_sizes, int n_in,
                              void* d_out, int out_size)
{
    const float* embs = (const float*)d_in[0];
    const float* Wix = (const float*)d_in[1];  const float* bix = (const float*)d_in[2];
    const float* Wfx = (const float*)d_in[3];  const float* bfx = (const float*)d_in[4];
    const float* Wux = (const float*)d_in[5];  const float* bux = (const float*)d_in[6];
    const float* Wox = (const float*)d_in[7];  const float* box_ = (const float*)d_in[8];
    const float* Wih = (const float*)d_in[9];  const float* bih = (const float*)d_in[10];
    const float* Wfh = (const float*)d_in[11]; const float* bfh = (const float*)d_in[12];
    const float* Wuh = (const float*)d_in[13]; const float* buh = (const float*)d_in[14];
    const float* Woh = (const float*)d_in[15]; const float* boh = (const float*)d_in[16];
    float* out = (float*)d_out;

    float *pE2, *pX, *pH2, *pHS2, *pWxp, *pWhp, *pbx, *pP, *pF;
    cudaGetSymbolAddress((void**)&pE2,  g_E2);
    cudaGetSymbolAddress((void**)&pX,   g_X);
    cudaGetSymbolAddress((void**)&pH2,  g_H2);
    cudaGetSymbolAddress((void**)&pHS2, g_HS2);
    cudaGetSymbolAddress((void**)&pWxp, g_Wxp);
    cudaGetSymbolAddress((void**)&pWhp, g_Whp);
    cudaGetSymbolAddress((void**)&pbx,  g_bx);
    cudaGetSymbolAddress((void**)&pP,   g_P);
    cudaGetSymbolAddress((void**)&pF,   g_F);

    static const int SIZES[9] = {65536, 16384, 4096, 1024, 256, 64, 16, 4, 1};
    static const int OFF[9]   = {0, 65536, 81920, 86016, 87040, 87296, 87360, 87376, 87380};
    const int SMEM  = 3 * 4672 * 4;   // 56064 B (generic gemm)
    const int SMEML = 3 * 8896 * 4;   // 106752 B (leaf-fused gemm)

    cudaFuncSetAttribute(gemm_tf32<true>,
                         cudaFuncAttributeMaxDynamicSharedMemorySize, SMEM);
    cudaFuncSetAttribute(gemm_tf32<false>,
                         cudaFuncAttributeMaxDynamicSharedMemorySize, SMEM);
    cudaFuncSetAttribute(gemm_leaf,
                         cudaFuncAttributeMaxDynamicSharedMemorySize, SMEML);

    // 1. pre-round + tile embs; pack weights
    round_embs_kernel<<<(688 * 19 * 1024 + 255) / 256, 256>>>(embs);
    pack_kernel<<<512, 256>>>(Wix, bix, Wfx, bfx, Wux, bux, Wox, box_,
                              Wih, bih, Wfh, bfh, Wuh, buh, Woh, boh);

    // 2a. leaves: fused X-projection + gates (no X round-trip)
    gemm_leaf<<<1024, 256, SMEML>>>(pE2, pWxp, out);

    // 2b. internal nodes: X projections, all 4 gates
    {
        dim3 grid(176, 4);
        gemm_tf32<true><<<grid, 256, SMEM>>>(pE2 + (size_t)512 * 19 * 2048, 19, pWxp, 0,
                                             pX + (size_t)65536 * 640, 640, pbx, 19);
    }

    // 3. levels 1..3: GEMM path
    for (int d = 1; d <= 3; d++) {
        int n  = SIZES[d];
        int np = SIZES[d - 1];
        hsum_kernel<<<((n >> 7) * 10 * 1024 + 255) / 256, 256>>>(OFF[d - 1], n);
        {   // P = h_sum @ [W_ih|W_uh|W_oh]
            dim3 grid(n / 128, 3);
            gemm_tf32<false><<<grid, 256, SMEM>>>(pHS2, 10, pWhp, 0, pP, 480, nullptr, 10);
        }
        {   // F = h_children @ W_fh  (B cols 480..639)
            dim3 grid(np / 128, 1);
            gemm_tf32<false><<<grid, 256, SMEM>>>(pH2 + (size_t)OFF[d - 1] * 160, 10,
                                                  pWhp, 480, pF, 160, nullptr, 10);
        }
        level_kernel<<<(n * 160 + 255) / 256, 256>>>(out, OFF[d], OFF[d - 1], n);
    }

    // 4. levels 4..8: fused fp32 kernels (n = 256, 64, 16, 4, 1)
    for (int d = 4; d <= 8; d++)
        small_level_kernel<<<SIZES[d], 160>>>(out, OFF[d], OFF[d - 1]);
}